// round 6
// baseline (speedup 1.0000x reference)
#include <cuda_runtime.h>
#include <math.h>

#define NB 32
#define NA 3
#define NH 52
#define NW 52
#define NG 50
#define NC 80
#define ATTRS 85
#define HW (NH * NW)              // 2704
#define F4C (HW / 4)              // 676
#define TPB 256
#define CPB 1024
#define BPS 3
#define NCONF (NB * NA * BPS)     // 288
#define NTGT (NB * NG)            // 1600
#define NITEMS (NTGT * ATTRS)     // 136000
#define IPT 2                     // items per thread
#define NWIN ((NITEMS + TPB*IPT - 1) / (TPB*IPT))   // 266
#define GRID2 (NCONF + NWIN)      // 554
#define CELLS (NB * NA * HW)      // 259584

// per-target params (written fully by k_prep every call)
__device__ int    g_tbase[NTGT];     // element offset of channel 0 for winner cell
__device__ float4 g_tbox[NTGT];      // tx, ty, tw, th
__device__ int    g_tcls[NTGT];
__device__ int    g_alive[NTGT];
__device__ float        g_part[GRID2 * 8];
__device__ unsigned int g_done;      // zero-init; last block restores zero

__constant__ float c_aw[3] = {1.25f, 2.0f, 4.125f};
__constant__ float c_ah[3] = {1.625f, 3.75f, 2.875f};

// min(softplus(x), 100) == bce(sigm(x), 0) with torch's -100 log clamp
__device__ __forceinline__ float sp(float x) {
    float r = fmaxf(x, 0.0f) + __logf(1.0f + __expf(-fabsf(x)));
    return fminf(r, 100.0f);
}

// ---------------- kernel 1: per-target params + dedup ----------------
__global__ void __launch_bounds__(64)
k_prep(const float* __restrict__ tg) {
    const int b = blockIdx.x;
    __shared__ int s_key[NG];
    if (threadIdx.x < NG) {
        const int t_i = threadIdx.x;
        const float* t = tg + (size_t)(b * NG + t_i) * 5;
        float gx = t[1] * ((float)NW / 416.0f);
        float gy = t[2] * ((float)NH / 416.0f);
        float gw = t[3] * ((float)NW / 416.0f);
        float gh = t[4] * ((float)NH / 416.0f);
        int gi = min(max((int)gx, 0), NW - 1);
        int gj = min(max((int)gy, 0), NH - 1);
        int cell = gj * NW + gi;
        float area_g = (gw + 1.0f) * (gh + 1.0f);
        float best_iou = -1.0f;
        int best = 0;
#pragma unroll
        for (int k = 0; k < 3; k++) {
            float iw = fmaxf(fminf(gw, c_aw[k]) + 1.0f, 0.0f);
            float ih = fmaxf(fminf(gh, c_ah[k]) + 1.0f, 0.0f);
            float inter = iw * ih;
            float area_k = (c_aw[k] + 1.0f) * (c_ah[k] + 1.0f);
            float iou = inter / (area_g + area_k - inter + 1e-16f);
            if (iou > best_iou) { best_iou = iou; best = k; }  // first-max = jnp.argmax
        }
        s_key[t_i] = best * HW + cell;
        const int gidx = b * NG + t_i;
        g_tbase[gidx] = (b * 255 + best * ATTRS) * HW + cell;
        g_tbox[gidx] = make_float4(gx - (float)gi, gy - (float)gj,
                                   logf(gw / c_aw[best] + 1e-16f),
                                   logf(gh / c_ah[best] + 1e-16f));
        g_tcls[gidx] = min(max((int)t[0], 0), NC - 1);
    }
    __syncthreads();
    if (threadIdx.x < NG) {
        int alive = 1;
        int key = s_key[threadIdx.x];
        for (int t2 = threadIdx.x + 1; t2 < NG; t2++)
            if (s_key[t2] == key) alive = 0;   // later scatter overwrites = max-g wins
        g_alive[b * NG + threadIdx.x] = alive;
    }
}

// ---------------- kernel 2: dense conf + flat winner gather ----------------
__global__ void __launch_bounds__(TPB)
k_main(const float* __restrict__ in, const float* __restrict__ tg,
       float* __restrict__ out) {
    __shared__ float sacc[8];
    __shared__ double dred[TPB];
    __shared__ unsigned int s_last;
    if (threadIdx.x < 8) sacc[threadIdx.x] = 0.0f;

    if (blockIdx.x < NCONF) {
        // ---- conf / noobj ----
        const int slice = blockIdx.x / BPS;
        const int pblk  = blockIdx.x % BPS;
        const int b = slice / NA;
        const int a = slice % NA;
        const int w0 = pblk * CPB;

        __shared__ unsigned char ssup[CPB];
        for (int i = threadIdx.x; i < CPB; i += TPB) ssup[i] = 0;
        __syncthreads();

        if (threadIdx.x < NG) {
            const float* t = tg + (size_t)(b * NG + threadIdx.x) * 5;
            float gx = t[1] * ((float)NW / 416.0f);
            float gy = t[2] * ((float)NH / 416.0f);
            float gw = t[3] * ((float)NW / 416.0f);
            float gh = t[4] * ((float)NH / 416.0f);
            int gi = min(max((int)gx, 0), NW - 1);
            int gj = min(max((int)gy, 0), NH - 1);
            int cell = gj * NW + gi;
            if (cell >= w0 && cell < w0 + CPB) {
                float area_g = (gw + 1.0f) * (gh + 1.0f);
                float iw = fmaxf(fminf(gw, c_aw[a]) + 1.0f, 0.0f);
                float ih = fmaxf(fminf(gh, c_ah[a]) + 1.0f, 0.0f);
                float inter = iw * ih;
                float area_a = (c_aw[a] + 1.0f) * (c_ah[a] + 1.0f);
                float iou = inter / (area_g + area_a - inter + 1e-16f);
                if (iou > 0.5f) ssup[cell - w0] = 1;
            }
        }
        __syncthreads();

        float snoobj = 0.f;
        const float* confc = in + (size_t)(b * 255 + a * ATTRS + 4) * HW;
        const int f = (w0 >> 2) + threadIdx.x;
        if (f < F4C) {
            float4 cv = reinterpret_cast<const float4*>(confc)[f];
            const int lb = threadIdx.x * 4;
            if (!ssup[lb + 0]) snoobj += sp(cv.x);
            if (!ssup[lb + 1]) snoobj += sp(cv.y);
            if (!ssup[lb + 2]) snoobj += sp(cv.z);
            if (!ssup[lb + 3]) snoobj += sp(cv.w);
        }
        unsigned lane = threadIdx.x & 31;
#pragma unroll
        for (int o = 16; o > 0; o >>= 1) snoobj += __shfl_down_sync(0xffffffffu, snoobj, o);
        if (lane == 0 && snoobj != 0.0f) atomicAdd(&sacc[5], snoobj);
    } else {
        // ---- flat winner gather: 2 independent items per thread ----
        const int wb = blockIdx.x - NCONF;
        float ax = 0.f, ay = 0.f, aw2 = 0.f, ah2 = 0.f, ac = 0.f;
        float acls = 0.f, np = 0.f;
#pragma unroll
        for (int i = 0; i < IPT; i++) {
            const int item = (wb * IPT + i) * TPB + threadIdx.x;
            if (item >= NITEMS) continue;
            const int tgt = item / ATTRS;
            const int ch  = item % ATTRS;
            if (!g_alive[tgt]) continue;
            float x = __ldg(in + (size_t)g_tbase[tgt] + (size_t)ch * HW);
            if (ch >= 5) {
                acls += sp((ch - 5 == g_tcls[tgt]) ? -x : x);
            } else if (ch == 0) {
                float tx = g_tbox[tgt].x;
                ax += tx * sp(-x) + (1.0f - tx) * sp(x);
                np += 1.0f;                         // count alive once per target
            } else if (ch == 1) {
                float ty = g_tbox[tgt].y;
                ay += ty * sp(-x) + (1.0f - ty) * sp(x);
            } else if (ch == 2) {
                float d = x - g_tbox[tgt].z; aw2 += d * d;
            } else if (ch == 3) {
                float d = x - g_tbox[tgt].w; ah2 += d * d;
            } else {
                ac += sp(-x);                       // bce(conf, 1)
            }
        }
        float vals[8] = {ax, ay, aw2, ah2, ac, 0.f, acls, np};
        unsigned lane = threadIdx.x & 31;
#pragma unroll
        for (int k = 0; k < 8; k++) {
            float v = vals[k];
#pragma unroll
            for (int o = 16; o > 0; o >>= 1) v += __shfl_down_sync(0xffffffffu, v, o);
            if (lane == 0 && v != 0.0f) atomicAdd(&sacc[k], v);
        }
    }
    __syncthreads();
    if (threadIdx.x < 8) g_part[blockIdx.x * 8 + threadIdx.x] = sacc[threadIdx.x];

    // ---- last-block final reduction ----
    if (threadIdx.x == 0) {
        __threadfence();
        unsigned int v = atomicAdd(&g_done, 1u);
        s_last = (v == (unsigned int)(GRID2 - 1)) ? 1u : 0u;
    }
    __syncthreads();
    if (s_last) {
        const int comp = threadIdx.x & 7;
        const int row  = threadIdx.x >> 3;
        double acc = 0.0;
        for (int i = row; i < GRID2; i += 32)
            acc += (double)g_part[i * 8 + comp];
        dred[threadIdx.x] = acc;
        __syncthreads();
        if (threadIdx.x < 8) {
            double s = 0.0;
#pragma unroll
            for (int r = 0; r < 32; r++) s += dred[r * 8 + threadIdx.x];
            dred[threadIdx.x] = s;
        }
        __syncthreads();
        if (threadIdx.x == 0) {
            const double N = (double)CELLS;
            double lx = dred[0] / N;
            double ly = dred[1] / N;
            double lw = dred[2] / N;
            double lh = dred[3] / N;
            double lconf = dred[4] / N + 0.5 * (dred[5] / N);
            double denom = dred[7] * (double)NC;
            if (denom < 1.0) denom = 1.0;
            double lcls = dred[6] / denom;
            out[0] = (float)(2.5 * (lx + ly) + 2.5 * (lw + lh) + lconf + lcls);
            g_done = 0u;
            __threadfence();
        }
    }
}

extern "C" void kernel_launch(void* const* d_in, const int* in_sizes, int n_in,
                              void* d_out, int out_size) {
    const float* inp = (const float*)d_in[0];   // [32,255,52,52]
    const float* tgt = (const float*)d_in[1];   // [32,50,5]
    k_prep<<<NB, 64>>>(tgt);
    k_main<<<GRID2, TPB>>>(inp, tgt, (float*)d_out);
}

// round 7
// speedup vs baseline: 1.1557x; 1.1557x over previous
#include <cuda_runtime.h>
#include <math.h>

#define NB 32
#define NA 3
#define NH 52
#define NW 52
#define NG 50
#define NC 80
#define ATTRS 85
#define HW (NH * NW)              // 2704
#define F4C (HW / 4)              // 676
#define TPB 256
#define CPB 1024
#define BPS 3
#define NCONF (NB * NA * BPS)     // 288
#define TGT_PER_WB 3              // targets per winner block (3*85=255 <= 256)
#define WB_PER_B 17               // ceil(50/3)
#define NWIN (NB * WB_PER_B)      // 544
#define GRID1 (NCONF + NWIN)      // 832
#define CELLS (NB * NA * HW)      // 259584

__device__ float g_part[GRID1 * 8];   // fully overwritten every call; no atomics

__constant__ float c_aw[3] = {1.25f, 2.0f, 4.125f};
__constant__ float c_ah[3] = {1.625f, 3.75f, 2.875f};

// min(softplus(x), 100) == bce(sigm(x), 0) with torch's -100 log clamp
__device__ __forceinline__ float sp(float x) {
    float r = fmaxf(x, 0.0f) + __logf(1.0f + __expf(-fabsf(x)));
    return fminf(r, 100.0f);
}

__global__ void __launch_bounds__(TPB)
k_main(const float* __restrict__ in, const float* __restrict__ tg) {
    __shared__ float sacc[8];
    if (threadIdx.x < 8) sacc[threadIdx.x] = 0.0f;

    if (blockIdx.x < NCONF) {
        // ================= CONF / NOOBJ BLOCK =================
        const int slice = blockIdx.x / BPS;
        const int pblk  = blockIdx.x % BPS;
        const int b = slice / NA;
        const int a = slice % NA;
        const int w0 = pblk * CPB;

        __shared__ unsigned char ssup[CPB];
        for (int i = threadIdx.x; i < CPB; i += TPB) ssup[i] = 0;
        __syncthreads();

        if (threadIdx.x < NG) {
            const float* t = tg + (size_t)(b * NG + threadIdx.x) * 5;
            float gx = t[1] * ((float)NW / 416.0f);
            float gy = t[2] * ((float)NH / 416.0f);
            float gw = t[3] * ((float)NW / 416.0f);
            float gh = t[4] * ((float)NH / 416.0f);
            int gi = min(max((int)gx, 0), NW - 1);
            int gj = min(max((int)gy, 0), NH - 1);
            int cell = gj * NW + gi;
            if (cell >= w0 && cell < w0 + CPB) {
                float area_g = (gw + 1.0f) * (gh + 1.0f);
                float iw = fmaxf(fminf(gw, c_aw[a]) + 1.0f, 0.0f);
                float ih = fmaxf(fminf(gh, c_ah[a]) + 1.0f, 0.0f);
                float inter = iw * ih;
                float area_a = (c_aw[a] + 1.0f) * (c_ah[a] + 1.0f);
                float iou = inter / (area_g + area_a - inter + 1e-16f);
                if (iou > 0.5f) ssup[cell - w0] = 1;
            }
        }
        __syncthreads();

        float snoobj = 0.f;
        const float* confc = in + (size_t)(b * 255 + a * ATTRS + 4) * HW;
        const int f = (w0 >> 2) + threadIdx.x;
        if (f < F4C) {
            float4 cv = reinterpret_cast<const float4*>(confc)[f];
            const int lb = threadIdx.x * 4;
            if (!ssup[lb + 0]) snoobj += sp(cv.x);
            if (!ssup[lb + 1]) snoobj += sp(cv.y);
            if (!ssup[lb + 2]) snoobj += sp(cv.z);
            if (!ssup[lb + 3]) snoobj += sp(cv.w);
        }
        unsigned lane = threadIdx.x & 31;
#pragma unroll
        for (int o = 16; o > 0; o >>= 1) snoobj += __shfl_down_sync(0xffffffffu, snoobj, o);
        if (lane == 0 && snoobj != 0.0f) atomicAdd(&sacc[5], snoobj);
    } else {
        // ================= WINNER BLOCK: 3 targets, 1 load/thread =================
        const int wb  = blockIdx.x - NCONF;
        const int b   = wb / WB_PER_B;
        const int lo  = (wb % WB_PER_B) * TGT_PER_WB;

        __shared__ int    s_base[NG];
        __shared__ float4 s_box[NG];     // tx, ty, tw, th
        __shared__ int    s_cls[NG];
        __shared__ int    s_key[NG];
        __shared__ unsigned char s_alive[NG];

        if (threadIdx.x < NG) {
            const int t_i = threadIdx.x;
            const float* t = tg + (size_t)(b * NG + t_i) * 5;
            float gx = t[1] * ((float)NW / 416.0f);
            float gy = t[2] * ((float)NH / 416.0f);
            float gw = t[3] * ((float)NW / 416.0f);
            float gh = t[4] * ((float)NH / 416.0f);
            int gi = min(max((int)gx, 0), NW - 1);
            int gj = min(max((int)gy, 0), NH - 1);
            int cell = gj * NW + gi;
            float area_g = (gw + 1.0f) * (gh + 1.0f);
            float best_iou = -1.0f;
            int best = 0;
#pragma unroll
            for (int k = 0; k < 3; k++) {
                float iw = fmaxf(fminf(gw, c_aw[k]) + 1.0f, 0.0f);
                float ih = fmaxf(fminf(gh, c_ah[k]) + 1.0f, 0.0f);
                float inter = iw * ih;
                float area_k = (c_aw[k] + 1.0f) * (c_ah[k] + 1.0f);
                float iou = inter / (area_g + area_k - inter + 1e-16f);
                if (iou > best_iou) { best_iou = iou; best = k; }  // first-max = jnp.argmax
            }
            s_key[t_i]  = best * HW + cell;
            s_base[t_i] = (b * 255 + best * ATTRS) * HW + cell;
            s_box[t_i]  = make_float4(gx - (float)gi, gy - (float)gj,
                                      logf(gw / c_aw[best] + 1e-16f),
                                      logf(gh / c_ah[best] + 1e-16f));
            s_cls[t_i]  = min(max((int)t[0], 0), NC - 1);
        }
        __syncthreads();
        if (threadIdx.x < NG) {
            unsigned char alive = 1;
            int key = s_key[threadIdx.x];
            for (int t2 = threadIdx.x + 1; t2 < NG; t2++)
                if (s_key[t2] == key) alive = 0;   // later scatter overwrites = max-g
            s_alive[threadIdx.x] = alive;
        }
        __syncthreads();

        float ax = 0.f, ay = 0.f, aw2 = 0.f, ah2 = 0.f, ac = 0.f;
        float acls = 0.f, np = 0.f;
        if (threadIdx.x < TGT_PER_WB * ATTRS) {
            const int tl  = threadIdx.x / ATTRS;
            const int ch  = threadIdx.x % ATTRS;
            const int tgt = lo + tl;
            if (tgt < NG && s_alive[tgt]) {
                float x = __ldg(in + (size_t)s_base[tgt] + (size_t)ch * HW);
                if (ch >= 5) {
                    acls = sp((ch - 5 == s_cls[tgt]) ? -x : x);
                } else if (ch == 0) {
                    float tx = s_box[tgt].x;
                    ax = tx * sp(-x) + (1.0f - tx) * sp(x);
                    np = 1.0f;                      // alive target counted once
                } else if (ch == 1) {
                    float ty = s_box[tgt].y;
                    ay = ty * sp(-x) + (1.0f - ty) * sp(x);
                } else if (ch == 2) {
                    float d = x - s_box[tgt].z; aw2 = d * d;
                } else if (ch == 3) {
                    float d = x - s_box[tgt].w; ah2 = d * d;
                } else {
                    ac = sp(-x);                    // bce(conf, 1)
                }
            }
        }
        float vals[8] = {ax, ay, aw2, ah2, ac, 0.f, acls, np};
        unsigned lane = threadIdx.x & 31;
#pragma unroll
        for (int k = 0; k < 8; k++) {
            float v = vals[k];
#pragma unroll
            for (int o = 16; o > 0; o >>= 1) v += __shfl_down_sync(0xffffffffu, v, o);
            if (lane == 0 && v != 0.0f) atomicAdd(&sacc[k], v);
        }
    }
    __syncthreads();
    if (threadIdx.x < 8) g_part[blockIdx.x * 8 + threadIdx.x] = sacc[threadIdx.x];
}

__global__ void __launch_bounds__(TPB)
k_reduce(float* __restrict__ out) {
    __shared__ double dred[TPB];
    const int comp = threadIdx.x & 7;
    const int row  = threadIdx.x >> 3;   // 0..31
    double acc = 0.0;
    for (int i = row; i < GRID1; i += 32)
        acc += (double)g_part[i * 8 + comp];
    dred[threadIdx.x] = acc;
    __syncthreads();
    if (threadIdx.x < 8) {
        double s = 0.0;
#pragma unroll
        for (int r = 0; r < 32; r++) s += dred[r * 8 + threadIdx.x];
        dred[threadIdx.x] = s;
    }
    __syncthreads();
    if (threadIdx.x == 0) {
        const double N = (double)CELLS;
        double lx = dred[0] / N;
        double ly = dred[1] / N;
        double lw = dred[2] / N;
        double lh = dred[3] / N;
        double lconf = dred[4] / N + 0.5 * (dred[5] / N);
        double denom = dred[7] * (double)NC;
        if (denom < 1.0) denom = 1.0;
        double lcls = dred[6] / denom;
        out[0] = (float)(2.5 * (lx + ly) + 2.5 * (lw + lh) + lconf + lcls);
    }
}

extern "C" void kernel_launch(void* const* d_in, const int* in_sizes, int n_in,
                              void* d_out, int out_size) {
    const float* inp = (const float*)d_in[0];   // [32,255,52,52]
    const float* tgt = (const float*)d_in[1];   // [32,50,5]
    k_main<<<GRID1, TPB>>>(inp, tgt);
    k_reduce<<<1, TPB>>>((float*)d_out);
}

// round 8
// speedup vs baseline: 1.4532x; 1.2574x over previous
#include <cuda_runtime.h>
#include <math.h>

#define NB 32
#define NA 3
#define NH 52
#define NW 52
#define NG 50
#define NC 80
#define ATTRS 85
#define HW (NH * NW)              // 2704
#define F4C (HW / 4)              // 676
#define TPB 256
#define NCONF (NB * NA)           // 96 conf blocks (one per slice)
#define TGT_PER_WB 10
#define WB_PER_B (NG / TGT_PER_WB)  // 5
#define NWIN (NB * WB_PER_B)      // 160
#define GRID (NCONF + NWIN)       // 256
#define NITEMS_WB (TGT_PER_WB * ATTRS)  // 850
#define IPT 4                     // ceil(850/256)
#define CELLS (NB * NA * HW)      // 259584

// acc: 0=x 1=y 2=w 3=h 4=conf_obj 5=noobj 6=cls 7=npos  (zero-init; last block resets)
__device__ float        g_acc[8];
__device__ unsigned int g_done;

__constant__ float c_aw[3] = {1.25f, 2.0f, 4.125f};
__constant__ float c_ah[3] = {1.625f, 3.75f, 2.875f};

// min(softplus(x), 100) == bce(sigm(x), 0) with torch's -100 log clamp
__device__ __forceinline__ float sp(float x) {
    float r = fmaxf(x, 0.0f) + __logf(1.0f + __expf(-fabsf(x)));
    return fminf(r, 100.0f);
}

__global__ void __launch_bounds__(TPB)
k_main(const float* __restrict__ in, const float* __restrict__ tg,
       float* __restrict__ out) {
    __shared__ float sacc[8];
    __shared__ unsigned int s_last;
    if (threadIdx.x < 8) sacc[threadIdx.x] = 0.0f;

    if (blockIdx.x < NCONF) {
        // ================= CONF / NOOBJ BLOCK: one (b,a) slice =================
        const int b = blockIdx.x / NA;
        const int a = blockIdx.x % NA;

        __shared__ unsigned int ssup32[F4C];           // 2704 bytes as 676 words
        unsigned char* ssup = (unsigned char*)ssup32;
#pragma unroll
        for (int i = threadIdx.x; i < F4C; i += TPB) ssup32[i] = 0u;
        __syncthreads();

        if (threadIdx.x < NG) {
            const float* t = tg + (size_t)(b * NG + threadIdx.x) * 5;
            float gx = t[1] * ((float)NW / 416.0f);
            float gy = t[2] * ((float)NH / 416.0f);
            float gw = t[3] * ((float)NW / 416.0f);
            float gh = t[4] * ((float)NH / 416.0f);
            int gi = min(max((int)gx, 0), NW - 1);
            int gj = min(max((int)gy, 0), NH - 1);
            float area_g = (gw + 1.0f) * (gh + 1.0f);
            float iw = fmaxf(fminf(gw, c_aw[a]) + 1.0f, 0.0f);
            float ih = fmaxf(fminf(gh, c_ah[a]) + 1.0f, 0.0f);
            float inter = iw * ih;
            float area_a = (c_aw[a] + 1.0f) * (c_ah[a] + 1.0f);
            float iou = inter / (area_g + area_a - inter + 1e-16f);
            if (iou > 0.5f) ssup[gj * NW + gi] = 1;
        }
        __syncthreads();

        float snoobj = 0.f;
        const float* confc = in + (size_t)(b * 255 + a * ATTRS + 4) * HW;
#pragma unroll
        for (int f = threadIdx.x; f < F4C; f += TPB) {
            float4 cv = reinterpret_cast<const float4*>(confc)[f];
            const int lb = f * 4;
            if (!ssup[lb + 0]) snoobj += sp(cv.x);
            if (!ssup[lb + 1]) snoobj += sp(cv.y);
            if (!ssup[lb + 2]) snoobj += sp(cv.z);
            if (!ssup[lb + 3]) snoobj += sp(cv.w);
        }
        unsigned lane = threadIdx.x & 31;
#pragma unroll
        for (int o = 16; o > 0; o >>= 1) snoobj += __shfl_down_sync(0xffffffffu, snoobj, o);
        if (lane == 0 && snoobj != 0.0f) atomicAdd(&sacc[5], snoobj);
    } else {
        // ================= WINNER BLOCK: 10 targets, 4 gathers/thread =============
        const int wb  = blockIdx.x - NCONF;
        const int b   = wb / WB_PER_B;
        const int lo  = (wb % WB_PER_B) * TGT_PER_WB;

        __shared__ int    s_base[NG];
        __shared__ float4 s_box[NG];        // tx, ty, tw, th
        __shared__ int    s_cls[NG];
        __shared__ int    s_key[NG];
        __shared__ unsigned char s_alive[NG];

        if (threadIdx.x < NG) {
            const int t_i = threadIdx.x;
            const float* t = tg + (size_t)(b * NG + t_i) * 5;
            float gx = t[1] * ((float)NW / 416.0f);
            float gy = t[2] * ((float)NH / 416.0f);
            float gw = t[3] * ((float)NW / 416.0f);
            float gh = t[4] * ((float)NH / 416.0f);
            int gi = min(max((int)gx, 0), NW - 1);
            int gj = min(max((int)gy, 0), NH - 1);
            int cell = gj * NW + gi;
            float area_g = (gw + 1.0f) * (gh + 1.0f);
            float best_iou = -1.0f;
            int best = 0;
#pragma unroll
            for (int k = 0; k < 3; k++) {
                float iw = fmaxf(fminf(gw, c_aw[k]) + 1.0f, 0.0f);
                float ih = fmaxf(fminf(gh, c_ah[k]) + 1.0f, 0.0f);
                float inter = iw * ih;
                float area_k = (c_aw[k] + 1.0f) * (c_ah[k] + 1.0f);
                float iou = inter / (area_g + area_k - inter + 1e-16f);
                if (iou > best_iou) { best_iou = iou; best = k; }  // first-max = jnp.argmax
            }
            s_key[t_i]  = best * HW + cell;
            s_base[t_i] = (b * 255 + best * ATTRS) * HW + cell;
            s_box[t_i]  = make_float4(gx - (float)gi, gy - (float)gj,
                                      logf(gw / c_aw[best] + 1e-16f),
                                      logf(gh / c_ah[best] + 1e-16f));
            s_cls[t_i]  = min(max((int)t[0], 0), NC - 1);
        }
        __syncthreads();
        if (threadIdx.x < NG) {
            unsigned char alive = 1;
            int key = s_key[threadIdx.x];
            for (int t2 = threadIdx.x + 1; t2 < NG; t2++)
                if (s_key[t2] == key) alive = 0;   // later scatter overwrites = max-g
            s_alive[threadIdx.x] = alive;
        }
        __syncthreads();

        // front-batched gather: 4 independent predicated loads per thread
        float xv[IPT];
        int   tgi[IPT], chi[IPT];
#pragma unroll
        for (int i = 0; i < IPT; i++) {
            const int w = threadIdx.x + i * TPB;
            const bool valid = w < NITEMS_WB;
            const int tgt = lo + (valid ? w / ATTRS : 0);
            const int ch  = valid ? w % ATTRS : 0;
            const bool live = valid && s_alive[tgt];
            tgi[i] = live ? tgt : -1;
            chi[i] = ch;
            xv[i] = live ? __ldg(in + (size_t)s_base[tgt] + (size_t)ch * HW) : 0.0f;
        }
        float ax = 0.f, ay = 0.f, aw2 = 0.f, ah2 = 0.f, ac = 0.f;
        float acls = 0.f, np = 0.f;
#pragma unroll
        for (int i = 0; i < IPT; i++) {
            const int tgt = tgi[i];
            if (tgt < 0) continue;
            const float x = xv[i];
            const int ch = chi[i];
            if (ch >= 5) {
                acls += sp((ch - 5 == s_cls[tgt]) ? -x : x);
            } else if (ch == 0) {
                float tx = s_box[tgt].x;
                ax += tx * sp(-x) + (1.0f - tx) * sp(x);
                np += 1.0f;                          // alive target counted once
            } else if (ch == 1) {
                float ty = s_box[tgt].y;
                ay += ty * sp(-x) + (1.0f - ty) * sp(x);
            } else if (ch == 2) {
                float d = x - s_box[tgt].z; aw2 += d * d;
            } else if (ch == 3) {
                float d = x - s_box[tgt].w; ah2 += d * d;
            } else {
                ac += sp(-x);                        // bce(conf, 1)
            }
        }
        float vals[7] = {ax, ay, aw2, ah2, ac, acls, np};
        const int map[7] = {0, 1, 2, 3, 4, 6, 7};
        unsigned lane = threadIdx.x & 31;
#pragma unroll
        for (int k = 0; k < 7; k++) {
            float v = vals[k];
#pragma unroll
            for (int o = 16; o > 0; o >>= 1) v += __shfl_down_sync(0xffffffffu, v, o);
            if (lane == 0 && v != 0.0f) atomicAdd(&sacc[map[k]], v);
        }
    }
    __syncthreads();

    // ---- 8 global float REDs per block (no return, cheap), then done-ticket ----
    if (threadIdx.x < 8) {
        float v = sacc[threadIdx.x];
        if (v != 0.0f) atomicAdd(&g_acc[threadIdx.x], v);
    }
    if (threadIdx.x == 0) {
        __threadfence();
        unsigned int v = atomicAdd(&g_done, 1u);
        s_last = (v == (unsigned int)(GRID - 1)) ? 1u : 0u;
    }
    __syncthreads();
    if (s_last && threadIdx.x == 0) {
        const double N = (double)CELLS;
        double lx = (double)g_acc[0] / N;
        double ly = (double)g_acc[1] / N;
        double lw = (double)g_acc[2] / N;
        double lh = (double)g_acc[3] / N;
        double lconf = (double)g_acc[4] / N + 0.5 * ((double)g_acc[5] / N);
        double denom = (double)g_acc[7] * (double)NC;
        if (denom < 1.0) denom = 1.0;
        double lcls = (double)g_acc[6] / denom;
        out[0] = (float)(2.5 * (lx + ly) + 2.5 * (lw + lh) + lconf + lcls);
#pragma unroll
        for (int k = 0; k < 8; k++) g_acc[k] = 0.0f;   // restore pristine state
        g_done = 0u;
        __threadfence();
    }
}

extern "C" void kernel_launch(void* const* d_in, const int* in_sizes, int n_in,
                              void* d_out, int out_size) {
    const float* inp = (const float*)d_in[0];   // [32,255,52,52]
    const float* tgt = (const float*)d_in[1];   // [32,50,5]
    k_main<<<GRID, TPB>>>(inp, tgt, (float*)d_out);
}

// round 9
// speedup vs baseline: 1.4752x; 1.0151x over previous
#include <cuda_runtime.h>
#include <math.h>

#define NB 32
#define NA 3
#define NH 52
#define NW 52
#define NG 50
#define NC 80
#define ATTRS 85
#define HW (NH * NW)              // 2704
#define F4C (HW / 4)              // 676
#define TPB 256
#define BPS 3
#define CPB 1024
#define NCONF (NB * NA * BPS)     // 288
#define TGT_PER_WB 10
#define WB_PER_B (NG / TGT_PER_WB)  // 5
#define NWIN (NB * WB_PER_B)      // 160
#define GRID (NCONF + NWIN)       // 448
#define NITEMS_WB (TGT_PER_WB * ATTRS)  // 850
#define IPT 4
#define CELLS (NB * NA * HW)      // 259584

// acc: 0=x 1=y 2=w 3=h 4=conf_obj 5=noobj 6=cls 7=npos (zero-init; last block resets)
__device__ float        g_acc[8];
__device__ unsigned int g_done;

__constant__ float c_aw[3] = {1.25f, 2.0f, 4.125f};
__constant__ float c_ah[3] = {1.625f, 3.75f, 2.875f};

// softplus via identity chain; full version (rarely used)
__device__ __forceinline__ float sp(float x) {
    return fmaxf(x, 0.0f) + __logf(1.0f + __expf(-fabsf(x)));
}
// the "u" factor: 1 + e^-|x|  (its log is the nonlinear part of softplus)
__device__ __forceinline__ float spu(float x) {
    return 1.0f + __expf(-fabsf(x));
}

__global__ void __launch_bounds__(TPB)
k_main(const float* __restrict__ in, const float* __restrict__ tg,
       float* __restrict__ out) {
    __shared__ float sacc[8];
    __shared__ unsigned int s_last;
    if (threadIdx.x < 8) sacc[threadIdx.x] = 0.0f;

    if (blockIdx.x < NCONF) {
        // ============ CONF / NOOBJ BLOCK: 1024-cell window of one slice ============
        const int slice = blockIdx.x / BPS;
        const int pblk  = blockIdx.x % BPS;
        const int b = slice / NA;
        const int a = slice % NA;
        const int w0 = pblk * CPB;

        __shared__ unsigned char ssup[CPB];
        for (int i = threadIdx.x; i < CPB; i += TPB) ssup[i] = 0;
        __syncthreads();

        if (threadIdx.x < NG) {
            const float* t = tg + (size_t)(b * NG + threadIdx.x) * 5;
            float gx = t[1] * ((float)NW / 416.0f);
            float gy = t[2] * ((float)NH / 416.0f);
            float gw = t[3] * ((float)NW / 416.0f);
            float gh = t[4] * ((float)NH / 416.0f);
            int gi = min(max((int)gx, 0), NW - 1);
            int gj = min(max((int)gy, 0), NH - 1);
            int cell = gj * NW + gi;
            if (cell >= w0 && cell < w0 + CPB) {
                float area_g = (gw + 1.0f) * (gh + 1.0f);
                float iw = fmaxf(fminf(gw, c_aw[a]) + 1.0f, 0.0f);
                float ih = fmaxf(fminf(gh, c_ah[a]) + 1.0f, 0.0f);
                float inter = iw * ih;
                float area_a = (c_aw[a] + 1.0f) * (c_ah[a] + 1.0f);
                float iou = inter / (area_g + area_a - inter + 1e-16f);
                if (iou > 0.5f) ssup[cell - w0] = 1;
            }
        }
        __syncthreads();

        // noobj = sum sp(x) over unsuppressed cells;
        // per float4: linear parts + ONE log of the product of u-factors
        float snoobj = 0.f;
        const float* confc = in + (size_t)(b * 255 + a * ATTRS + 4) * HW;
        const int f = (w0 >> 2) + threadIdx.x;
        if (f < F4C) {
            float4 cv = reinterpret_cast<const float4*>(confc)[f];
            const int lb = threadIdx.x * 4;
            float lin = 0.0f, prod = 1.0f;
            if (!ssup[lb + 0]) { lin += fmaxf(cv.x, 0.0f); prod *= spu(cv.x); }
            if (!ssup[lb + 1]) { lin += fmaxf(cv.y, 0.0f); prod *= spu(cv.y); }
            if (!ssup[lb + 2]) { lin += fmaxf(cv.z, 0.0f); prod *= spu(cv.z); }
            if (!ssup[lb + 3]) { lin += fmaxf(cv.w, 0.0f); prod *= spu(cv.w); }
            snoobj = lin + __logf(prod);
        }
        unsigned lane = threadIdx.x & 31;
#pragma unroll
        for (int o = 16; o > 0; o >>= 1) snoobj += __shfl_down_sync(0xffffffffu, snoobj, o);
        if (lane == 0 && snoobj != 0.0f) atomicAdd(&sacc[5], snoobj);
    } else {
        // ============ WINNER BLOCK: 10 targets, 4 gathers/thread ============
        const int wb  = blockIdx.x - NCONF;
        const int b   = wb / WB_PER_B;
        const int lo  = (wb % WB_PER_B) * TGT_PER_WB;

        __shared__ int    s_base[NG];
        __shared__ float4 s_box[NG];       // tx, ty, tw, th
        __shared__ int    s_cls[NG];
        __shared__ int    s_key[NG];
        __shared__ unsigned char s_alive[NG];

        if (threadIdx.x < NG) {
            const int t_i = threadIdx.x;
            const float* t = tg + (size_t)(b * NG + t_i) * 5;
            float gx = t[1] * ((float)NW / 416.0f);
            float gy = t[2] * ((float)NH / 416.0f);
            float gw = t[3] * ((float)NW / 416.0f);
            float gh = t[4] * ((float)NH / 416.0f);
            int gi = min(max((int)gx, 0), NW - 1);
            int gj = min(max((int)gy, 0), NH - 1);
            int cell = gj * NW + gi;
            float area_g = (gw + 1.0f) * (gh + 1.0f);
            float best_iou = -1.0f;
            int best = 0;
#pragma unroll
            for (int k = 0; k < 3; k++) {
                float iw = fmaxf(fminf(gw, c_aw[k]) + 1.0f, 0.0f);
                float ih = fmaxf(fminf(gh, c_ah[k]) + 1.0f, 0.0f);
                float inter = iw * ih;
                float area_k = (c_aw[k] + 1.0f) * (c_ah[k] + 1.0f);
                float iou = inter / (area_g + area_k - inter + 1e-16f);
                if (iou > best_iou) { best_iou = iou; best = k; }  // first-max = jnp.argmax
            }
            s_key[t_i]  = best * HW + cell;
            s_base[t_i] = (b * 255 + best * ATTRS) * HW + cell;
            s_box[t_i]  = make_float4(gx - (float)gi, gy - (float)gj,
                                      logf(gw / c_aw[best] + 1e-16f),
                                      logf(gh / c_ah[best] + 1e-16f));
            s_cls[t_i]  = min(max((int)t[0], 0), NC - 1);
        }
        __syncthreads();
        if (threadIdx.x < NG) {
            unsigned char alive = 1;
            int key = s_key[threadIdx.x];
            for (int t2 = threadIdx.x + 1; t2 < NG; t2++)
                if (s_key[t2] == key) alive = 0;   // later scatter overwrites = max-g
            s_alive[threadIdx.x] = alive;
        }
        __syncthreads();

        // front-batched gather: 4 independent predicated loads
        float xv[IPT];
        int   tgi[IPT], chi[IPT];
#pragma unroll
        for (int i = 0; i < IPT; i++) {
            const int w = threadIdx.x + i * TPB;
            const bool valid = w < NITEMS_WB;
            const int tgt = lo + (valid ? w / ATTRS : 0);
            const int ch  = valid ? w % ATTRS : 0;
            const bool live = valid && s_alive[tgt];
            tgi[i] = live ? tgt : -1;
            chi[i] = ch;
            xv[i] = live ? __ldg(in + (size_t)s_base[tgt] + (size_t)ch * HW) : 0.0f;
        }
        // bce(sigm(x), t) = sp(x) - t*x; cls logs merged into one product
        float ax = 0.f, ay = 0.f, aw2 = 0.f, ah2 = 0.f, ac = 0.f;
        float acls = 0.f, np = 0.f;
        float prodc = 1.0f;
#pragma unroll
        for (int i = 0; i < IPT; i++) {
            const int tgt = tgi[i];
            if (tgt < 0) continue;
            const float x = xv[i];
            const int ch = chi[i];
            if (ch >= 5) {
                float t = (ch - 5 == s_cls[tgt]) ? 1.0f : 0.0f;
                acls += fmaxf(x, 0.0f) - t * x;
                prodc *= spu(x);
            } else if (ch == 0) {
                ax += sp(x) - s_box[tgt].x * x;
                np += 1.0f;
            } else if (ch == 1) {
                ay += sp(x) - s_box[tgt].y * x;
            } else if (ch == 2) {
                float d = x - s_box[tgt].z; aw2 += d * d;
            } else if (ch == 3) {
                float d = x - s_box[tgt].w; ah2 += d * d;
            } else {
                ac += sp(x) - x;                    // bce(conf, 1) = sp(-x)
            }
        }
        acls += __logf(prodc);

        float vals[7] = {ax, ay, aw2, ah2, ac, acls, np};
        const int map[7] = {0, 1, 2, 3, 4, 6, 7};
        unsigned lane = threadIdx.x & 31;
#pragma unroll
        for (int k = 0; k < 7; k++) {
            float v = vals[k];
#pragma unroll
            for (int o = 16; o > 0; o >>= 1) v += __shfl_down_sync(0xffffffffu, v, o);
            if (lane == 0 && v != 0.0f) atomicAdd(&sacc[map[k]], v);
        }
    }
    __syncthreads();

    // ---- 8 global float REDs per block, then done-ticket; last block finalizes ----
    if (threadIdx.x < 8) {
        float v = sacc[threadIdx.x];
        if (v != 0.0f) atomicAdd(&g_acc[threadIdx.x], v);
    }
    if (threadIdx.x == 0) {
        __threadfence();
        unsigned int v = atomicAdd(&g_done, 1u);
        s_last = (v == (unsigned int)(GRID - 1)) ? 1u : 0u;
    }
    __syncthreads();
    if (s_last && threadIdx.x == 0) {
        const double N = (double)CELLS;
        double lx = (double)g_acc[0] / N;
        double ly = (double)g_acc[1] / N;
        double lw = (double)g_acc[2] / N;
        double lh = (double)g_acc[3] / N;
        double lconf = (double)g_acc[4] / N + 0.5 * ((double)g_acc[5] / N);
        double denom = (double)g_acc[7] * (double)NC;
        if (denom < 1.0) denom = 1.0;
        double lcls = (double)g_acc[6] / denom;
        out[0] = (float)(2.5 * (lx + ly) + 2.5 * (lw + lh) + lconf + lcls);
#pragma unroll
        for (int k = 0; k < 8; k++) g_acc[k] = 0.0f;   // restore pristine state
        g_done = 0u;
        __threadfence();
    }
}

extern "C" void kernel_launch(void* const* d_in, const int* in_sizes, int n_in,
                              void* d_out, int out_size) {
    const float* inp = (const float*)d_in[0];   // [32,255,52,52]
    const float* tgt = (const float*)d_in[1];   // [32,50,5]
    k_main<<<GRID, TPB>>>(inp, tgt, (float*)d_out);
}